// round 8
// baseline (speedup 1.0000x reference)
#include <cuda_runtime.h>
#include <stdint.h>

#define EE     100000
#define NNODE  50000
#define DIN    192
#define KNB    8
#define NTILES ((EE + 127) / 128)   // 782

// ---------------- scratch (device globals) ----------------
__device__ float g_qkv[EE * DIN];     // [E,192] = [q|k|v]
__device__ float g_att[EE * 64];      // [E,64]
__device__ float g_ef1[EE * 64];      // [E,64] layer-1 out (fp32 residual source)
__device__ float g_ef1r[EE * 64];     // tf32-rna rounded copy of g_ef1
__device__ float g_nfr[NNODE * 64];   // rounded node features
__device__ float g_efr[EE * 64];      // rounded edge features
__device__ float g_wr1[DIN * DIN];    // rounded concat [k][q|k|v], layer 1
__device__ float g_wr2[DIN * DIN];    // layer 2

// ---------------- helpers ----------------
__device__ __forceinline__ uint32_t f2tf(float x) {
    uint32_t u; asm("cvt.rna.tf32.f32 %0, %1;" : "=r"(u) : "f"(x)); return u;
}
__device__ __forceinline__ void mma8(float* c, const uint32_t* a, uint32_t b0, uint32_t b1) {
    asm volatile("mma.sync.aligned.m16n8k8.row.col.f32.tf32.tf32.f32 "
        "{%0,%1,%2,%3}, {%4,%5,%6,%7}, {%8,%9}, {%0,%1,%2,%3};"
        : "+f"(c[0]), "+f"(c[1]), "+f"(c[2]), "+f"(c[3])
        : "r"(a[0]), "r"(a[1]), "r"(a[2]), "r"(a[3]), "r"(b0), "r"(b1));
}
__device__ __forceinline__ void ldsm4(uint32_t* f, uint32_t addr) {
    asm volatile("ldmatrix.sync.aligned.m8n8.x4.shared.b16 {%0,%1,%2,%3}, [%4];"
        : "=r"(f[0]), "=r"(f[1]), "=r"(f[2]), "=r"(f[3]) : "r"(addr));
}
__device__ __forceinline__ void cpa16(uint32_t dst, const void* src, int srcsize) {
    asm volatile("cp.async.cg.shared.global [%0], [%1], 16, %2;"
        :: "r"(dst), "l"(src), "r"(srcsize) : "memory");
}
#define CP_COMMIT() asm volatile("cp.async.commit_group;" ::: "memory")
#define CP_WAIT(n)  asm volatile("cp.async.wait_group %0;" :: "n"(n) : "memory")

// ---------------- pre-rounding kernels ----------------
__global__ void round_copy_kernel(const float* __restrict__ src, float* __restrict__ dst, int n4) {
    int i = blockIdx.x * blockDim.x + threadIdx.x;
    if (i >= n4) return;
    float4 v = reinterpret_cast<const float4*>(src)[i];
    uint4 u = make_uint4(f2tf(v.x), f2tf(v.y), f2tf(v.z), f2tf(v.w));
    reinterpret_cast<uint4*>(dst)[i] = u;
}
__global__ void round_w_kernel(const float* __restrict__ wq, const float* __restrict__ wk,
                               const float* __restrict__ wv, float* __restrict__ dst) {
    int idx = blockIdx.x * blockDim.x + threadIdx.x;
    if (idx >= DIN * DIN) return;
    int k = idx / DIN, n = idx - k * DIN;
    float v = (n < 64) ? wq[k * 64 + n] : (n < 128) ? wk[k * 64 + (n - 64)] : wv[k * 64 + (n - 128)];
    dst[idx] = __uint_as_float(f2tf(v));
}

// ---------------- QKV smem geometry: full-K resident ----------------
#define ASTRIDE    196                    // A [m=128][k=192] m-major, pad 196
#define BSTR       104                    // B [k=192][n=96]  k-major, pad 104 (104%32==8)
#define A_WORDS_F  (128 * ASTRIDE)        // 25088
#define B_WORDS_F  (192 * BSTR)           // 19968
#define QKV_SMEM_BYTES ((A_WORDS_F + B_WORDS_F) * 4)   // 180224

// Wo kernel smem
#define WA_WORDS   (128 * 36)
#define WB_WORDS   (64 * 36)
#define WO_SMEM_BYTES ((2 * WA_WORDS + 2 * WB_WORDS) * 4)

// ======================================================================
// QKV GEMM, fused gather, full-K smem, 2 barriers total.
// BM=128, BN=96 (blockIdx.x&1 selects N-half), K=192.
// 256 threads, 8 warps as 2M x 4N, warp tile 64x24.
// All inputs pre-rounded tf32 -> cp.async raw copy lossless.
// ======================================================================
__global__ __launch_bounds__(256, 1) void qkv_mma_kernel(
    const float* __restrict__ efr, const float* __restrict__ nfr,
    const int* __restrict__ ei, const float* __restrict__ wr)
{
    extern __shared__ uint32_t smem[];
    uint32_t* As = smem;
    uint32_t* Bs = smem + A_WORDS_F;
    const uint32_t As_b = (uint32_t)__cvta_generic_to_shared(As);
    const uint32_t Bs_b = (uint32_t)__cvta_generic_to_shared(Bs);

    const int tid  = threadIdx.x;
    const int tile = blockIdx.x >> 1;
    const int n0   = (blockIdx.x & 1) * 96;
    const int m0   = tile * 128;

    // ---- A loader: row r = tid>>1, sel = tid&1 picks 48-col stripe per group ----
    const int r   = tid >> 1;
    const int sel = tid & 1;
    const int e   = m0 + r;
    const bool valid = (e < EE);
    const int ec  = valid ? e : (EE - 1);
    const int si  = ei[ec], di = ei[EE + ec];
    const float* tbl0 = efr + (size_t)ec * 64;
    const float* tbl1 = nfr + (size_t)si * 64;
    const float* tbl2 = nfr + (size_t)di * 64;
    const int ssz = valid ? 16 : 0;

    // ---- Group 0: all of B + A cols [sel*48, sel*48+48) (union over threads = cols 0..95) ----
    #pragma unroll
    for (int i = 0; i < 18; i++) {               // B: 192x96 floats = 4608 f4 / 256 thr
        int f = i * 256 + tid;
        int k = f / 24, n4 = (f % 24) * 4;
        cpa16(Bs_b + (k * BSTR + n4) * 4, wr + (size_t)k * DIN + n0 + n4, 16);
    }
    #pragma unroll
    for (int j = 0; j < 12; j++) {
        int col = sel * 48 + j * 4;
        const float* src = (col < 64) ? tbl0 + col : tbl1 + (col - 64);
        cpa16(As_b + (r * ASTRIDE + col) * 4, src, ssz);
    }
    CP_COMMIT();
    // ---- Group 1: A cols [96 + sel*48, +48) ----
    #pragma unroll
    for (int j = 0; j < 12; j++) {
        int col = 96 + sel * 48 + j * 4;
        const float* src = (col < 128) ? tbl1 + (col - 64) : tbl2 + (col - 128);
        cpa16(As_b + (r * ASTRIDE + col) * 4, src, ssz);
    }
    CP_COMMIT();

    // ---- warp layout: 2M x 4N, warp tile 64x24 ----
    const int wid = tid >> 5, lane = tid & 31;
    const int wm = (wid & 1) * 64, wn = (wid >> 1) * 24;
    const int g = lane >> 2, t4 = lane & 3;
    const int j8 = lane & 7, grp = lane >> 3;

    uint32_t aAddr[4];
    #pragma unroll
    for (int mt = 0; mt < 4; mt++) {
        int row = wm + mt * 16 + (grp & 1) * 8 + j8;
        int col = (grp >> 1) * 4;
        aAddr[mt] = As_b + (row * ASTRIDE + col) * 4;
    }
    const uint32_t* Bw = Bs + wn + g;

    float acc[4][3][4];
    #pragma unroll
    for (int i = 0; i < 4; i++)
        #pragma unroll
        for (int j = 0; j < 3; j++)
            #pragma unroll
            for (int q = 0; q < 4; q++) acc[i][j][q] = 0.f;

    // ---- phase 1: chunks 0..11 (cols 0..95) ----
    CP_WAIT(1);
    __syncthreads();
    #pragma unroll
    for (int c = 0; c < 12; c++) {
        uint32_t af[4][4];
        #pragma unroll
        for (int mt = 0; mt < 4; mt++) ldsm4(af[mt], aAddr[mt] + c * 32);
        const int kl = c * 8 + t4;
        uint32_t b0[3], b1[3];
        #pragma unroll
        for (int nt = 0; nt < 3; nt++) {
            b0[nt] = Bw[kl * BSTR + nt * 8];
            b1[nt] = Bw[(kl + 4) * BSTR + nt * 8];
        }
        #pragma unroll
        for (int mt = 0; mt < 4; mt++)
            #pragma unroll
            for (int nt = 0; nt < 3; nt++)
                mma8(acc[mt][nt], af[mt], b0[nt], b1[nt]);
    }
    // ---- phase 2: chunks 12..23 ----
    CP_WAIT(0);
    __syncthreads();
    #pragma unroll
    for (int c = 12; c < 24; c++) {
        uint32_t af[4][4];
        #pragma unroll
        for (int mt = 0; mt < 4; mt++) ldsm4(af[mt], aAddr[mt] + c * 32);
        const int kl = c * 8 + t4;
        uint32_t b0[3], b1[3];
        #pragma unroll
        for (int nt = 0; nt < 3; nt++) {
            b0[nt] = Bw[kl * BSTR + nt * 8];
            b1[nt] = Bw[(kl + 4) * BSTR + nt * 8];
        }
        #pragma unroll
        for (int mt = 0; mt < 4; mt++)
            #pragma unroll
            for (int nt = 0; nt < 3; nt++)
                mma8(acc[mt][nt], af[mt], b0[nt], b1[nt]);
    }

    // ---- epilogue ----
    #pragma unroll
    for (int mt = 0; mt < 4; mt++) {
        const int row = m0 + wm + mt * 16 + g;
        #pragma unroll
        for (int nt = 0; nt < 3; nt++) {
            const int col = n0 + wn + nt * 8 + t4 * 2;
            if (row < EE)
                *reinterpret_cast<float2*>(g_qkv + (size_t)row * DIN + col) =
                    make_float2(acc[mt][nt][0], acc[mt][nt][1]);
            if (row + 8 < EE)
                *reinterpret_cast<float2*>(g_qkv + (size_t)(row + 8) * DIN + col) =
                    make_float2(acc[mt][nt][2], acc[mt][nt][3]);
        }
    }
}

// ======================================================================
// Wo GEMM + residual: out = ef_in + g_att[E,64] @ Wo[64,64]
// ======================================================================
__global__ __launch_bounds__(256, 2) void wo_mma_kernel(
    const float* __restrict__ Wo,
    const float* __restrict__ ef_ext, float* __restrict__ out_ext,
    int use_ef1_in, int write_ef1)
{
    extern __shared__ uint32_t smem[];
    uint32_t* As = smem;
    uint32_t* Bs = smem + 2 * WA_WORDS;

    const int tid = threadIdx.x;
    const int m0  = blockIdx.x * 128;
    const float* ef_in = use_ef1_in ? (const float*)g_ef1 : ef_ext;
    float* out = write_ef1 ? (float*)g_ef1 : out_ext;

    const int r  = tid >> 1;
    const int e  = m0 + r;
    const int kb = (tid & 1) * 16;
    const bool valid = (e < EE);

    const int bk = tid & 31;
    const int bn = (tid >> 5) * 8;

    const int wid = tid >> 5, lane = tid & 31;
    const int wm = (wid & 3) * 32, wn = (wid >> 2) * 32;
    const int g = lane >> 2, t4 = lane & 3;
    const int j8 = lane & 7, grp = lane >> 3;

    const uint32_t As_b = (uint32_t)__cvta_generic_to_shared(As);
    const uint32_t Bs_b = (uint32_t)__cvta_generic_to_shared(Bs);
    uint32_t aAddr[2], bAddr[2];
    #pragma unroll
    for (int mt = 0; mt < 2; mt++) {
        int row = wm + mt * 16 + (grp & 1) * 8 + j8;
        int col = (grp >> 1) * 4;
        aAddr[mt] = As_b + (row * 36 + col) * 4;
    }
    #pragma unroll
    for (int p = 0; p < 2; p++) {
        int row = wn + p * 16 + (grp >> 1) * 8 + j8;
        int col = (grp & 1) * 4;
        bAddr[p] = Bs_b + (row * 36 + col) * 4;
    }

    float acc[2][4][4];
    #pragma unroll
    for (int i = 0; i < 2; i++)
        #pragma unroll
        for (int j = 0; j < 4; j++)
            #pragma unroll
            for (int q = 0; q < 4; q++) acc[i][j][q] = 0.f;

    float4 av[4], bv[2];
    auto ldg_tile = [&](int it) {
        const int k0 = it * 32;
        if (valid) {
            const float* base = g_att + (size_t)e * 64 + k0 + kb;
            #pragma unroll
            for (int c = 0; c < 4; c++) av[c] = *reinterpret_cast<const float4*>(base + c * 4);
        } else {
            #pragma unroll
            for (int c = 0; c < 4; c++) av[c] = make_float4(0.f, 0.f, 0.f, 0.f);
        }
        #pragma unroll
        for (int c = 0; c < 2; c++)
            bv[c] = *reinterpret_cast<const float4*>(Wo + (size_t)(k0 + bk) * 64 + bn + c * 4);
    };
    auto sts_tile = [&](int b) {
        uint32_t* Aw = As + b * WA_WORDS;
        uint32_t* Bw = Bs + b * WB_WORDS;
        #pragma unroll
        for (int c = 0; c < 4; c++) {
            uint4 u = make_uint4(f2tf(av[c].x), f2tf(av[c].y), f2tf(av[c].z), f2tf(av[c].w));
            *reinterpret_cast<uint4*>(&Aw[r * 36 + kb + c * 4]) = u;
        }
        #pragma unroll
        for (int c = 0; c < 2; c++) {
            float vv[4] = {bv[c].x, bv[c].y, bv[c].z, bv[c].w};
            #pragma unroll
            for (int j = 0; j < 4; j++) Bw[(bn + c * 4 + j) * 36 + bk] = f2tf(vv[j]);
        }
    };

    ldg_tile(0);
    sts_tile(0);
    ldg_tile(1);
    __syncthreads();

    #pragma unroll
    for (int i = 0; i < 2; i++) {
        const int cur = i & 1;
        const uint32_t aOff = cur * (WA_WORDS * 4);
        const uint32_t bOff = cur * (WB_WORDS * 4);
        #pragma unroll
        for (int ks = 0; ks < 4; ks++) {
            uint32_t af0[4], af1[4], bf0[4], bf1[4];
            ldsm4(af0, aAddr[0] + aOff + ks * 32);
            ldsm4(af1, aAddr[1] + aOff + ks * 32);
            ldsm4(bf0, bAddr[0] + bOff + ks * 32);
            ldsm4(bf1, bAddr[1] + bOff + ks * 32);
            mma8(acc[0][0], af0, bf0[0], bf0[1]);
            mma8(acc[0][1], af0, bf0[2], bf0[3]);
            mma8(acc[0][2], af0, bf1[0], bf1[1]);
            mma8(acc[0][3], af0, bf1[2], bf1[3]);
            mma8(acc[1][0], af1, bf0[0], bf0[1]);
            mma8(acc[1][1], af1, bf0[2], bf0[3]);
            mma8(acc[1][2], af1, bf1[0], bf1[1]);
            mma8(acc[1][3], af1, bf1[2], bf1[3]);
        }
        if (i == 0) {
            sts_tile(1);
            __syncthreads();
        }
    }

    #pragma unroll
    for (int mt = 0; mt < 2; mt++) {
        const int row = m0 + wm + mt * 16 + g;
        #pragma unroll
        for (int nt = 0; nt < 4; nt++) {
            const int col = wn + nt * 8 + t4 * 2;
            #pragma unroll
            for (int h = 0; h < 2; h++) {
                const int rw = row + h * 8;
                if (rw < EE) {
                    float2 rr = *reinterpret_cast<const float2*>(ef_in + (size_t)rw * 64 + col);
                    float ox = rr.x + acc[mt][nt][h * 2 + 0];
                    float oy = rr.y + acc[mt][nt][h * 2 + 1];
                    *reinterpret_cast<float2*>(out + (size_t)rw * 64 + col) = make_float2(ox, oy);
                    if (write_ef1)
                        *reinterpret_cast<float2*>(g_ef1r + (size_t)rw * 64 + col) =
                            make_float2(__uint_as_float(f2tf(ox)), __uint_as_float(f2tf(oy)));
                }
            }
        }
    }
}

// ---------------- attention: 2 edges per warp, float4 lanes ----------------
__global__ void attn_kernel(const int* __restrict__ adj_src) {
    int gw2 = (blockIdx.x * blockDim.x + threadIdx.x) >> 5;   // warp index
    int lane = threadIdx.x & 31;
    int sub = lane >> 4, l16 = lane & 15;
    int e = gw2 * 2 + sub;
    if (e >= EE) return;   // EE even + exact grid -> warp-uniform

    const float* qrow = g_qkv + (size_t)e * DIN;
    float4 q = *reinterpret_cast<const float4*>(qrow + 4 * l16);

    float sj[KNB];
    float4 vv[KNB];
    const int base = e * KNB;
    #pragma unroll
    for (int j = 0; j < KNB; j++) {
        int n = adj_src[base + j];
        const float* kr = g_qkv + (size_t)n * DIN + 64;
        float4 kk = *reinterpret_cast<const float4*>(kr + 4 * l16);
        vv[j] = *reinterpret_cast<const float4*>(kr + 64 + 4 * l16);
        float p = q.x * kk.x + q.y * kk.y + q.z * kk.z + q.w * kk.w;
        p += __shfl_xor_sync(0xffffffffu, p, 1);
        p += __shfl_xor_sync(0xffffffffu, p, 2);   // head-local (4 lanes = 16 floats)
        sj[j] = p * 0.25f;                          // 1/sqrt(16)
    }

    float m = sj[0];
    #pragma unroll
    for (int j = 1; j < KNB; j++) m = fmaxf(m, sj[j]);

    float denom = 0.f;
    float4 a = make_float4(0.f, 0.f, 0.f, 0.f);
    #pragma unroll
    for (int j = 0; j < KNB; j++) {
        float w = __expf(sj[j] - m);
        denom += w;
        a.x += w * vv[j].x; a.y += w * vv[j].y;
        a.z += w * vv[j].z; a.w += w * vv[j].w;
    }
    float inv = 1.0f / denom;
    *reinterpret_cast<float4*>(g_att + (size_t)e * 64 + 4 * l16) =
        make_float4(a.x * inv, a.y * inv, a.z * inv, a.w * inv);
}

// ---------------- launch ----------------
extern "C" void kernel_launch(void* const* d_in, const int* in_sizes, int n_in,
                              void* d_out, int out_size) {
    const float* nf      = (const float*)d_in[0];
    const float* ef      = (const float*)d_in[1];
    const int*   ei      = (const int*)d_in[2];
    const int*   adj_src = (const int*)d_in[4];
    const float* l1_Wq = (const float*)d_in[6];
    const float* l1_Wk = (const float*)d_in[7];
    const float* l1_Wv = (const float*)d_in[8];
    const float* l1_Wo = (const float*)d_in[9];
    const float* l2_Wq = (const float*)d_in[10];
    const float* l2_Wk = (const float*)d_in[11];
    const float* l2_Wv = (const float*)d_in[12];
    const float* l2_Wo = (const float*)d_in[13];
    float* out = (float*)d_out;

    static int attr_done = 0;
    if (!attr_done) {
        cudaFuncSetAttribute(qkv_mma_kernel, cudaFuncAttributeMaxDynamicSharedMemorySize, QKV_SMEM_BYTES);
        cudaFuncSetAttribute(wo_mma_kernel,  cudaFuncAttributeMaxDynamicSharedMemorySize, WO_SMEM_BYTES);
        attr_done = 1;
    }

    float *p_nfr, *p_efr, *p_ef1r, *p_wr1, *p_wr2;
    cudaGetSymbolAddress((void**)&p_nfr, g_nfr);
    cudaGetSymbolAddress((void**)&p_efr, g_efr);
    cudaGetSymbolAddress((void**)&p_ef1r, g_ef1r);
    cudaGetSymbolAddress((void**)&p_wr1, g_wr1);
    cudaGetSymbolAddress((void**)&p_wr2, g_wr2);

    const int gq  = NTILES * 2;          // 1564 (x>>1 = tile, x&1 = N-half)
    const int gwb = (EE + 127) / 128;
    const int attn_blocks = EE / 16;     // 2 edges/warp, 8 warps/block

    // pre-round GEMM inputs to tf32-rna (cp.async copies raw bits losslessly)
    round_copy_kernel<<<(NNODE * 16 + 255) / 256, 256>>>(nf, p_nfr, NNODE * 16);
    round_copy_kernel<<<(EE * 16 + 255) / 256, 256>>>(ef, p_efr, EE * 16);
    round_w_kernel<<<(DIN * DIN + 255) / 256, 256>>>(l1_Wq, l1_Wk, l1_Wv, p_wr1);
    round_w_kernel<<<(DIN * DIN + 255) / 256, 256>>>(l2_Wq, l2_Wk, l2_Wv, p_wr2);

    // layer 1
    qkv_mma_kernel<<<gq, 256, QKV_SMEM_BYTES>>>(p_efr, p_nfr, ei, p_wr1);
    attn_kernel<<<attn_blocks, 256>>>(adj_src);
    wo_mma_kernel<<<gwb, 256, WO_SMEM_BYTES>>>(l1_Wo, ef, nullptr, 0, 1);

    // layer 2
    qkv_mma_kernel<<<gq, 256, QKV_SMEM_BYTES>>>(p_ef1r, p_nfr, ei, p_wr2);
    attn_kernel<<<attn_blocks, 256>>>(adj_src);
    wo_mma_kernel<<<gwb, 256, WO_SMEM_BYTES>>>(l2_Wo, nullptr, out, 1, 0);
}

// round 9
// speedup vs baseline: 1.2966x; 1.2966x over previous
#include <cuda_runtime.h>
#include <stdint.h>

#define EE     100000
#define DIN    192
#define KNB    8

// ---------------- scratch (device globals) ----------------
__device__ float g_qkv[EE * DIN];   // [E,192] = [q|k|v]
__device__ float g_att[EE * 64];    // [E,64]
__device__ float g_ef1[EE * 64];    // [E,64] layer-1 out

// ---------------- helpers ----------------
__device__ __forceinline__ uint32_t f2tf(float x) {
    uint32_t u; asm("cvt.rna.tf32.f32 %0, %1;" : "=r"(u) : "f"(x)); return u;
}
__device__ __forceinline__ void mma8(float* c, const uint32_t* a, uint32_t b0, uint32_t b1) {
    asm volatile("mma.sync.aligned.m16n8k8.row.col.f32.tf32.tf32.f32 "
        "{%0,%1,%2,%3}, {%4,%5,%6,%7}, {%8,%9}, {%0,%1,%2,%3};"
        : "+f"(c[0]), "+f"(c[1]), "+f"(c[2]), "+f"(c[3])
        : "r"(a[0]), "r"(a[1]), "r"(a[2]), "r"(a[3]), "r"(b0), "r"(b1));
}
__device__ __forceinline__ void ldsm4(uint32_t* f, uint32_t addr) {
    asm volatile("ldmatrix.sync.aligned.m8n8.x4.shared.b16 {%0,%1,%2,%3}, [%4];"
        : "=r"(f[0]), "=r"(f[1]), "=r"(f[2]), "=r"(f[3]) : "r"(addr));
}

// ---------------- QKV kernel smem geometry (r4 proven) ----------------
#define BSTRIDE    200
#define B_WORDS_F  (192 * BSTRIDE)      // 38400
#define A_WORDS    (128 * 36)           // 4608
#define QKV_SMEM_WORDS (B_WORDS_F + 2 * A_WORDS)
#define QKV_SMEM_BYTES (QKV_SMEM_WORDS * 4)

// Wo kernel smem
#define WA_WORDS   (128 * 36)
#define WB_WORDS   (64 * 36)
#define WO_SMEM_BYTES ((2 * WA_WORDS + 2 * WB_WORDS) * 4)

// ======================================================================
// Fused QKV GEMM (r4): qkv[E,192] = concat(ef|ef1, nf[src], nf[dst]) @ [Wq|Wk|Wv]
// BM=128, BN=192, BK=32; 8 warps as 2M x 4N, warp tile 64x48.
// ======================================================================
__global__ __launch_bounds__(256, 1) void qkv_mma_kernel(
    const float* __restrict__ ef, const float* __restrict__ nf,
    const int* __restrict__ ei,
    const float* __restrict__ wq, const float* __restrict__ wk, const float* __restrict__ wv,
    int use_ef1)
{
    extern __shared__ uint32_t smem[];
    uint32_t* Bs = smem;                 // [192][200]
    uint32_t* As = smem + B_WORDS_F;     // [2][128*36]

    const int tid = threadIdx.x;
    const int m0  = blockIdx.x * 128;
    const float* efsrc = use_ef1 ? (const float*)g_ef1 : ef;

    const int r  = tid >> 1;
    const int e  = m0 + r;
    const int kb = (tid & 1) * 16;
    const bool valid = (e < EE);
    int si = 0, di = 0;
    if (valid) { si = ei[e]; di = ei[EE + e]; }

    const int wid = tid >> 5, lane = tid & 31;
    const int wm = (wid & 1) * 64, wn = (wid >> 1) * 48;
    const int g = lane >> 2, t4 = lane & 3;
    const int j8 = lane & 7, grp = lane >> 3;

    // ---- preload full B into smem (tf32) ----
    {
        #pragma unroll
        for (int w = 0; w < 3; w++) {
            const float* W = (w == 0) ? wq : (w == 1) ? wk : wv;
            #pragma unroll
            for (int j = 0; j < 12; j++) {
                int f = j * 256 + tid;
                int k = f >> 4;
                int n4 = (f & 15) * 4;
                float4 v = *reinterpret_cast<const float4*>(W + (size_t)k * 64 + n4);
                uint32_t* dst = Bs + k * BSTRIDE + w * 64 + n4;
                dst[0] = f2tf(v.x); dst[1] = f2tf(v.y);
                dst[2] = f2tf(v.z); dst[3] = f2tf(v.w);
            }
        }
    }

    const uint32_t As_b = (uint32_t)__cvta_generic_to_shared(As);
    uint32_t aAddr[4];
    #pragma unroll
    for (int mt = 0; mt < 4; mt++) {
        int row = wm + mt * 16 + (grp & 1) * 8 + j8;
        int col = (grp >> 1) * 4;
        aAddr[mt] = As_b + (row * 36 + col) * 4;
    }

    float acc[4][6][4];
    #pragma unroll
    for (int i = 0; i < 4; i++)
        #pragma unroll
        for (int j = 0; j < 6; j++)
            #pragma unroll
            for (int q = 0; q < 4; q++) acc[i][j][q] = 0.f;

    float4 av[4];
    auto ldg_tile = [&](int it) {
        const int k0 = it * 32;
        if (valid) {
            const int reg = k0 >> 6;
            const float* base = (reg == 0) ? efsrc + (size_t)e * 64
                              : (reg == 1) ? nf + (size_t)si * 64
                                           : nf + (size_t)di * 64;
            const int cb = (k0 & 32) + kb;
            #pragma unroll
            for (int c = 0; c < 4; c++) av[c] = *reinterpret_cast<const float4*>(base + cb + c * 4);
        } else {
            #pragma unroll
            for (int c = 0; c < 4; c++) av[c] = make_float4(0.f, 0.f, 0.f, 0.f);
        }
    };
    auto sts_tile = [&](int b) {
        uint32_t* Aw = As + b * A_WORDS;
        #pragma unroll
        for (int c = 0; c < 4; c++) {
            uint4 u = make_uint4(f2tf(av[c].x), f2tf(av[c].y), f2tf(av[c].z), f2tf(av[c].w));
            *reinterpret_cast<uint4*>(&Aw[r * 36 + kb + c * 4]) = u;
        }
    };

    const uint32_t* Bwp = Bs + wn + g;

    const int NIT = DIN / 32;   // 6
    ldg_tile(0);
    sts_tile(0);
    ldg_tile(1);
    __syncthreads();

    for (int i = 0; i < NIT; i++) {
        const int cur = i & 1;
        const uint32_t aOff = cur * (A_WORDS * 4);
        #pragma unroll
        for (int ks = 0; ks < 4; ks++) {
            const int kg = i * 32 + ks * 8 + t4;
            uint32_t af[4][4];
            #pragma unroll
            for (int mt = 0; mt < 4; mt++) ldsm4(af[mt], aAddr[mt] + aOff + ks * 32);
            uint32_t b0[6], b1[6];
            #pragma unroll
            for (int nt = 0; nt < 6; nt++) {
                b0[nt] = Bwp[kg * BSTRIDE + nt * 8];
                b1[nt] = Bwp[(kg + 4) * BSTRIDE + nt * 8];
            }
            #pragma unroll
            for (int mt = 0; mt < 4; mt++)
                #pragma unroll
                for (int nt = 0; nt < 6; nt++)
                    mma8(acc[mt][nt], af[mt], b0[nt], b1[nt]);
        }
        if (i + 1 < NIT) {
            sts_tile(cur ^ 1);
            if (i + 2 < NIT) ldg_tile(i + 2);
            __syncthreads();
        }
    }

    #pragma unroll
    for (int mt = 0; mt < 4; mt++) {
        const int row = m0 + wm + mt * 16 + g;
        #pragma unroll
        for (int nt = 0; nt < 6; nt++) {
            const int col = wn + nt * 8 + t4 * 2;
            if (row < EE)
                *reinterpret_cast<float2*>(g_qkv + (size_t)row * DIN + col) =
                    make_float2(acc[mt][nt][0], acc[mt][nt][1]);
            if (row + 8 < EE)
                *reinterpret_cast<float2*>(g_qkv + (size_t)(row + 8) * DIN + col) =
                    make_float2(acc[mt][nt][2], acc[mt][nt][3]);
        }
    }
}

// ======================================================================
// Wo GEMM + residual (r4): out = ef_in + g_att[E,64] @ Wo[64,64]
// ======================================================================
__global__ __launch_bounds__(256, 2) void wo_mma_kernel(
    const float* __restrict__ Wo,
    const float* __restrict__ ef_ext, float* __restrict__ out_ext,
    int use_ef1_in, int write_ef1)
{
    extern __shared__ uint32_t smem[];
    uint32_t* As = smem;
    uint32_t* Bs = smem + 2 * WA_WORDS;

    const int tid = threadIdx.x;
    const int m0  = blockIdx.x * 128;
    const float* ef_in = use_ef1_in ? (const float*)g_ef1 : ef_ext;
    float* out = write_ef1 ? (float*)g_ef1 : out_ext;

    const int r  = tid >> 1;
    const int e  = m0 + r;
    const int kb = (tid & 1) * 16;
    const bool valid = (e < EE);

    const int bk = tid & 31;
    const int bn = (tid >> 5) * 8;

    const int wid = tid >> 5, lane = tid & 31;
    const int wm = (wid & 3) * 32, wn = (wid >> 2) * 32;
    const int g = lane >> 2, t4 = lane & 3;
    const int j8 = lane & 7, grp = lane >> 3;

    const uint32_t As_b = (uint32_t)__cvta_generic_to_shared(As);
    const uint32_t Bs_b = (uint32_t)__cvta_generic_to_shared(Bs);
    uint32_t aAddr[2], bAddr[2];
    #pragma unroll
    for (int mt = 0; mt < 2; mt++) {
        int row = wm + mt * 16 + (grp & 1) * 8 + j8;
        int col = (grp >> 1) * 4;
        aAddr[mt] = As_b + (row * 36 + col) * 4;
    }
    #pragma unroll
    for (int p = 0; p < 2; p++) {
        int row = wn + p * 16 + (grp >> 1) * 8 + j8;
        int col = (grp & 1) * 4;
        bAddr[p] = Bs_b + (row * 36 + col) * 4;
    }

    float acc[2][4][4];
    #pragma unroll
    for (int i = 0; i < 2; i++)
        #pragma unroll
        for (int j = 0; j < 4; j++)
            #pragma unroll
            for (int q = 0; q < 4; q++) acc[i][j][q] = 0.f;

    float4 av[4], bv[2];
    auto ldg_tile = [&](int it) {
        const int k0 = it * 32;
        if (valid) {
            const float* base = g_att + (size_t)e * 64 + k0 + kb;
            #pragma unroll
            for (int c = 0; c < 4; c++) av[c] = *reinterpret_cast<const float4*>(base + c * 4);
        } else {
            #pragma unroll
            for (int c = 0; c < 4; c++) av[c] = make_float4(0.f, 0.f, 0.f, 0.f);
        }
        #pragma unroll
        for (int c = 0; c < 2; c++)
            bv[c] = *reinterpret_cast<const float4*>(Wo + (size_t)(k0 + bk) * 64 + bn + c * 4);
    };
    auto sts_tile = [&](int b) {
        uint32_t* Aw = As + b * WA_WORDS;
        uint32_t* Bw = Bs + b * WB_WORDS;
        #pragma unroll
        for (int c = 0; c < 4; c++) {
            uint4 u = make_uint4(f2tf(av[c].x), f2tf(av[c].y), f2tf(av[c].z), f2tf(av[c].w));
            *reinterpret_cast<uint4*>(&Aw[r * 36 + kb + c * 4]) = u;
        }
        #pragma unroll
        for (int c = 0; c < 2; c++) {
            float vv[4] = {bv[c].x, bv[c].y, bv[c].z, bv[c].w};
            #pragma unroll
            for (int j = 0; j < 4; j++) Bw[(bn + c * 4 + j) * 36 + bk] = f2tf(vv[j]);
        }
    };

    ldg_tile(0);
    sts_tile(0);
    ldg_tile(1);
    __syncthreads();

    #pragma unroll
    for (int i = 0; i < 2; i++) {
        const int cur = i & 1;
        const uint32_t aOff = cur * (WA_WORDS * 4);
        const uint32_t bOff = cur * (WB_WORDS * 4);
        #pragma unroll
        for (int ks = 0; ks < 4; ks++) {
            uint32_t af0[4], af1[4], bf0[4], bf1[4];
            ldsm4(af0, aAddr[0] + aOff + ks * 32);
            ldsm4(af1, aAddr[1] + aOff + ks * 32);
            ldsm4(bf0, bAddr[0] + bOff + ks * 32);
            ldsm4(bf1, bAddr[1] + bOff + ks * 32);
            mma8(acc[0][0], af0, bf0[0], bf0[1]);
            mma8(acc[0][1], af0, bf0[2], bf0[3]);
            mma8(acc[0][2], af0, bf1[0], bf1[1]);
            mma8(acc[0][3], af0, bf1[2], bf1[3]);
            mma8(acc[1][0], af1, bf0[0], bf0[1]);
            mma8(acc[1][1], af1, bf0[2], bf0[3]);
            mma8(acc[1][2], af1, bf1[0], bf1[1]);
            mma8(acc[1][3], af1, bf1[2], bf1[3]);
        }
        if (i == 0) {
            sts_tile(1);
            __syncthreads();
        }
    }

    #pragma unroll
    for (int mt = 0; mt < 2; mt++) {
        const int row = m0 + wm + mt * 16 + g;
        #pragma unroll
        for (int nt = 0; nt < 4; nt++) {
            const int col = wn + nt * 8 + t4 * 2;
            if (row < EE) {
                float2 rr = *reinterpret_cast<const float2*>(ef_in + (size_t)row * 64 + col);
                *reinterpret_cast<float2*>(out + (size_t)row * 64 + col) =
                    make_float2(rr.x + acc[mt][nt][0], rr.y + acc[mt][nt][1]);
            }
            if (row + 8 < EE) {
                float2 rr = *reinterpret_cast<const float2*>(ef_in + (size_t)(row + 8) * 64 + col);
                *reinterpret_cast<float2*>(out + (size_t)(row + 8) * 64 + col) =
                    make_float2(rr.x + acc[mt][nt][2], rr.y + acc[mt][nt][3]);
            }
        }
    }
}

// ---------------- attention: 2 edges per warp, float4 lanes (r8) ----------------
__global__ void attn_kernel(const int* __restrict__ adj_src) {
    int gw2 = (blockIdx.x * blockDim.x + threadIdx.x) >> 5;
    int lane = threadIdx.x & 31;
    int sub = lane >> 4, l16 = lane & 15;
    int e = gw2 * 2 + sub;
    if (e >= EE) return;

    const float* qrow = g_qkv + (size_t)e * DIN;
    float4 q = *reinterpret_cast<const float4*>(qrow + 4 * l16);

    float sj[KNB];
    float4 vv[KNB];
    const int base = e * KNB;
    #pragma unroll
    for (int j = 0; j < KNB; j++) {
        int n = adj_src[base + j];
        const float* kr = g_qkv + (size_t)n * DIN + 64;
        float4 kk = *reinterpret_cast<const float4*>(kr + 4 * l16);
        vv[j] = *reinterpret_cast<const float4*>(kr + 64 + 4 * l16);
        float p = q.x * kk.x + q.y * kk.y + q.z * kk.z + q.w * kk.w;
        p += __shfl_xor_sync(0xffffffffu, p, 1);
        p += __shfl_xor_sync(0xffffffffu, p, 2);   // head-local (4 lanes = 16 floats)
        sj[j] = p * 0.25f;                          // 1/sqrt(16)
    }

    float m = sj[0];
    #pragma unroll
    for (int j = 1; j < KNB; j++) m = fmaxf(m, sj[j]);

    float denom = 0.f;
    float4 a = make_float4(0.f, 0.f, 0.f, 0.f);
    #pragma unroll
    for (int j = 0; j < KNB; j++) {
        float w = __expf(sj[j] - m);
        denom += w;
        a.x += w * vv[j].x; a.y += w * vv[j].y;
        a.z += w * vv[j].z; a.w += w * vv[j].w;
    }
    float inv = 1.0f / denom;
    *reinterpret_cast<float4*>(g_att + (size_t)e * 64 + 4 * l16) =
        make_float4(a.x * inv, a.y * inv, a.z * inv, a.w * inv);
}

// ---------------- launch ----------------
extern "C" void kernel_launch(void* const* d_in, const int* in_sizes, int n_in,
                              void* d_out, int out_size) {
    const float* nf      = (const float*)d_in[0];
    const float* ef      = (const float*)d_in[1];
    const int*   ei      = (const int*)d_in[2];
    const int*   adj_src = (const int*)d_in[4];
    const float* l1_Wq = (const float*)d_in[6];
    const float* l1_Wk = (const float*)d_in[7];
    const float* l1_Wv = (const float*)d_in[8];
    const float* l1_Wo = (const float*)d_in[9];
    const float* l2_Wq = (const float*)d_in[10];
    const float* l2_Wk = (const float*)d_in[11];
    const float* l2_Wv = (const float*)d_in[12];
    const float* l2_Wo = (const float*)d_in[13];
    float* out = (float*)d_out;

    static int attr_done = 0;
    if (!attr_done) {
        cudaFuncSetAttribute(qkv_mma_kernel, cudaFuncAttributeMaxDynamicSharedMemorySize, QKV_SMEM_BYTES);
        cudaFuncSetAttribute(wo_mma_kernel,  cudaFuncAttributeMaxDynamicSharedMemorySize, WO_SMEM_BYTES);
        attr_done = 1;
    }

    const int gq  = (EE + 127) / 128;
    const int gwb = (EE + 127) / 128;
    const int attn_blocks = EE / 16;     // 2 edges/warp, 8 warps/block

    // layer 1
    qkv_mma_kernel<<<gq, 256, QKV_SMEM_BYTES>>>(ef, nf, ei, l1_Wq, l1_Wk, l1_Wv, 0);
    attn_kernel<<<attn_blocks, 256>>>(adj_src);
    wo_mma_kernel<<<gwb, 256, WO_SMEM_BYTES>>>(l1_Wo, ef, nullptr, 0, 1);

    // layer 2
    qkv_mma_kernel<<<gq, 256, QKV_SMEM_BYTES>>>(ef, nf, ei, l2_Wq, l2_Wk, l2_Wv, 1);
    attn_kernel<<<attn_blocks, 256>>>(adj_src);
    wo_mma_kernel<<<gwb, 256, WO_SMEM_BYTES>>>(l2_Wo, nullptr, out, 1, 0);
}

// round 10
// speedup vs baseline: 1.3276x; 1.0239x over previous
#include <cuda_runtime.h>
#include <stdint.h>

#define EE     100000
#define DIN    192
#define KNB    8

// ---------------- scratch (device globals) ----------------
__device__ float g_qkv[EE * DIN];   // [E,192] = [q|k|v]
__device__ float g_ef1[EE * 64];    // [E,64] layer-1 out

// ---------------- helpers ----------------
__device__ __forceinline__ uint32_t f2tf(float x) {
    uint32_t u; asm("cvt.rna.tf32.f32 %0, %1;" : "=r"(u) : "f"(x)); return u;
}
__device__ __forceinline__ void mma8(float* c, const uint32_t* a, uint32_t b0, uint32_t b1) {
    asm volatile("mma.sync.aligned.m16n8k8.row.col.f32.tf32.tf32.f32 "
        "{%0,%1,%2,%3}, {%4,%5,%6,%7}, {%8,%9}, {%0,%1,%2,%3};"
        : "+f"(c[0]), "+f"(c[1]), "+f"(c[2]), "+f"(c[3])
        : "r"(a[0]), "r"(a[1]), "r"(a[2]), "r"(a[3]), "r"(b0), "r"(b1));
}
__device__ __forceinline__ void ldsm4(uint32_t* f, uint32_t addr) {
    asm volatile("ldmatrix.sync.aligned.m8n8.x4.shared.b16 {%0,%1,%2,%3}, [%4];"
        : "=r"(f[0]), "=r"(f[1]), "=r"(f[2]), "=r"(f[3]) : "r"(addr));
}

// ---------------- QKV kernel smem geometry (r4/r9 proven) ----------------
#define BSTRIDE    200
#define B_WORDS_F  (192 * BSTRIDE)      // 38400
#define A_WORDS    (128 * 36)           // 4608
#define QKV_SMEM_BYTES ((B_WORDS_F + 2 * A_WORDS) * 4)

// ---------------- fused attn+wo smem geometry ----------------
#define FSTRIDE    68                    // 68 % 32 == 4 -> conflict-free ldsm/STS
#define FA_WORDS   (128 * FSTRIDE)       // 8704
#define FB_WORDS   (64 * FSTRIDE)        // 4352
#define FUSED_SMEM_BYTES ((FA_WORDS + FB_WORDS) * 4)   // 52224

// ======================================================================
// Fused QKV GEMM (r4/r9 proven): qkv = concat(ef|ef1, nf[src], nf[dst]) @ [Wq|Wk|Wv]
// BM=128, BN=192, BK=32; 8 warps as 2M x 4N, warp tile 64x48.
// ======================================================================
__global__ __launch_bounds__(256, 1) void qkv_mma_kernel(
    const float* __restrict__ ef, const float* __restrict__ nf,
    const int* __restrict__ ei,
    const float* __restrict__ wq, const float* __restrict__ wk, const float* __restrict__ wv,
    int use_ef1)
{
    extern __shared__ uint32_t smem[];
    uint32_t* Bs = smem;                 // [192][200]
    uint32_t* As = smem + B_WORDS_F;     // [2][128*36]

    const int tid = threadIdx.x;
    const int m0  = blockIdx.x * 128;
    const float* efsrc = use_ef1 ? (const float*)g_ef1 : ef;

    const int r  = tid >> 1;
    const int e  = m0 + r;
    const int kb = (tid & 1) * 16;
    const bool valid = (e < EE);
    int si = 0, di = 0;
    if (valid) { si = ei[e]; di = ei[EE + e]; }

    const int wid = tid >> 5, lane = tid & 31;
    const int wm = (wid & 1) * 64, wn = (wid >> 1) * 48;
    const int g = lane >> 2, t4 = lane & 3;
    const int j8 = lane & 7, grp = lane >> 3;

    // ---- preload full B into smem (tf32) ----
    {
        #pragma unroll
        for (int w = 0; w < 3; w++) {
            const float* W = (w == 0) ? wq : (w == 1) ? wk : wv;
            #pragma unroll
            for (int j = 0; j < 12; j++) {
                int f = j * 256 + tid;
                int k = f >> 4;
                int n4 = (f & 15) * 4;
                float4 v = *reinterpret_cast<const float4*>(W + (size_t)k * 64 + n4);
                uint32_t* dst = Bs + k * BSTRIDE + w * 64 + n4;
                dst[0] = f2tf(v.x); dst[1] = f2tf(v.y);
                dst[2] = f2tf(v.z); dst[3] = f2tf(v.w);
            }
        }
    }

    const uint32_t As_b = (uint32_t)__cvta_generic_to_shared(As);
    uint32_t aAddr[4];
    #pragma unroll
    for (int mt = 0; mt < 4; mt++) {
        int row = wm + mt * 16 + (grp & 1) * 8 + j8;
        int col = (grp >> 1) * 4;
        aAddr[mt] = As_b + (row * 36 + col) * 4;
    }

    float acc[4][6][4];
    #pragma unroll
    for (int i = 0; i < 4; i++)
        #pragma unroll
        for (int j = 0; j < 6; j++)
            #pragma unroll
            for (int q = 0; q < 4; q++) acc[i][j][q] = 0.f;

    float4 av[4];
    auto ldg_tile = [&](int it) {
        const int k0 = it * 32;
        if (valid) {
            const int reg = k0 >> 6;
            const float* base = (reg == 0) ? efsrc + (size_t)e * 64
                              : (reg == 1) ? nf + (size_t)si * 64
                                           : nf + (size_t)di * 64;
            const int cb = (k0 & 32) + kb;
            #pragma unroll
            for (int c = 0; c < 4; c++) av[c] = *reinterpret_cast<const float4*>(base + cb + c * 4);
        } else {
            #pragma unroll
            for (int c = 0; c < 4; c++) av[c] = make_float4(0.f, 0.f, 0.f, 0.f);
        }
    };
    auto sts_tile = [&](int b) {
        uint32_t* Aw = As + b * A_WORDS;
        #pragma unroll
        for (int c = 0; c < 4; c++) {
            uint4 u = make_uint4(f2tf(av[c].x), f2tf(av[c].y), f2tf(av[c].z), f2tf(av[c].w));
            *reinterpret_cast<uint4*>(&Aw[r * 36 + kb + c * 4]) = u;
        }
    };

    const uint32_t* Bwp = Bs + wn + g;

    const int NIT = DIN / 32;   // 6
    ldg_tile(0);
    sts_tile(0);
    ldg_tile(1);
    __syncthreads();

    for (int i = 0; i < NIT; i++) {
        const int cur = i & 1;
        const uint32_t aOff = cur * (A_WORDS * 4);
        #pragma unroll
        for (int ks = 0; ks < 4; ks++) {
            const int kg = i * 32 + ks * 8 + t4;
            uint32_t af[4][4];
            #pragma unroll
            for (int mt = 0; mt < 4; mt++) ldsm4(af[mt], aAddr[mt] + aOff + ks * 32);
            uint32_t b0[6], b1[6];
            #pragma unroll
            for (int nt = 0; nt < 6; nt++) {
                b0[nt] = Bwp[kg * BSTRIDE + nt * 8];
                b1[nt] = Bwp[(kg + 4) * BSTRIDE + nt * 8];
            }
            #pragma unroll
            for (int mt = 0; mt < 4; mt++)
                #pragma unroll
                for (int nt = 0; nt < 6; nt++)
                    mma8(acc[mt][nt], af[mt], b0[nt], b1[nt]);
        }
        if (i + 1 < NIT) {
            sts_tile(cur ^ 1);
            if (i + 2 < NIT) ldg_tile(i + 2);
            __syncthreads();
        }
    }

    #pragma unroll
    for (int mt = 0; mt < 4; mt++) {
        const int row = m0 + wm + mt * 16 + g;
        #pragma unroll
        for (int nt = 0; nt < 6; nt++) {
            const int col = wn + nt * 8 + t4 * 2;
            if (row < EE)
                *reinterpret_cast<float2*>(g_qkv + (size_t)row * DIN + col) =
                    make_float2(acc[mt][nt][0], acc[mt][nt][1]);
            if (row + 8 < EE)
                *reinterpret_cast<float2*>(g_qkv + (size_t)(row + 8) * DIN + col) =
                    make_float2(acc[mt][nt][2], acc[mt][nt][3]);
        }
    }
}

// ======================================================================
// FUSED attention + Wo GEMM + residual.
// Phase 1: 128 dst edges/CTA, attention (2 edges/warp x 8 iters) -> As tf32
// Phase 2: out = ef_in + As[128,64] @ Wo[64,64]
// ======================================================================
__global__ __launch_bounds__(256, 2) void attn_wo_kernel(
    const float* __restrict__ Wo,
    const int* __restrict__ adj_src,
    const float* __restrict__ ef_ext, float* __restrict__ out_ext,
    int use_ef1_in, int write_ef1)
{
    extern __shared__ uint32_t smem[];
    uint32_t* As = smem;                // [128][68] attention rows, tf32
    uint32_t* Bs = smem + FA_WORDS;     // [64][68]  Wo transposed [n][k], tf32

    const int tid = threadIdx.x;
    const int m0  = blockIdx.x * 128;
    const float* ef_in = use_ef1_in ? (const float*)g_ef1 : ef_ext;
    float* out = write_ef1 ? (float*)g_ef1 : out_ext;

    const int wid = tid >> 5, lane = tid & 31;

    // ---- load Wo -> Bs [n][k] (transposed, stride 68) ----
    {
        const int bk = tid & 31;
        const int bn = (tid >> 5) * 8;
        #pragma unroll
        for (int k0 = 0; k0 < 64; k0 += 32) {
            float4 bv0 = *reinterpret_cast<const float4*>(Wo + (size_t)(k0 + bk) * 64 + bn);
            float4 bv1 = *reinterpret_cast<const float4*>(Wo + (size_t)(k0 + bk) * 64 + bn + 4);
            float vv[8] = {bv0.x, bv0.y, bv0.z, bv0.w, bv1.x, bv1.y, bv1.z, bv1.w};
            #pragma unroll
            for (int j = 0; j < 8; j++)
                Bs[(bn + j) * FSTRIDE + k0 + bk] = f2tf(vv[j]);
        }
    }

    // ---- phase 1: attention into As ----
    {
        const int sub = lane >> 4, l16 = lane & 15;
        #pragma unroll
        for (int iter = 0; iter < 8; iter++) {
            const int el = iter * 16 + wid * 2 + sub;
            const int e = m0 + el;
            const int ec = (e < EE) ? e : (EE - 1);   // clamp: keeps shuffles convergent

            const float* qrow = g_qkv + (size_t)ec * DIN;
            float4 q = *reinterpret_cast<const float4*>(qrow + 4 * l16);

            float sj[KNB];
            float4 vv[KNB];
            const int base = ec * KNB;
            #pragma unroll
            for (int j = 0; j < KNB; j++) {
                int n = adj_src[base + j];
                const float* kr = g_qkv + (size_t)n * DIN + 64;
                float4 kk = *reinterpret_cast<const float4*>(kr + 4 * l16);
                vv[j] = *reinterpret_cast<const float4*>(kr + 64 + 4 * l16);
                float p = q.x * kk.x + q.y * kk.y + q.z * kk.z + q.w * kk.w;
                p += __shfl_xor_sync(0xffffffffu, p, 1);
                p += __shfl_xor_sync(0xffffffffu, p, 2);   // head-local (4 lanes)
                sj[j] = p * 0.25f;                          // 1/sqrt(16)
            }

            float m = sj[0];
            #pragma unroll
            for (int j = 1; j < KNB; j++) m = fmaxf(m, sj[j]);

            float denom = 0.f;
            float4 a = make_float4(0.f, 0.f, 0.f, 0.f);
            #pragma unroll
            for (int j = 0; j < KNB; j++) {
                float w = __expf(sj[j] - m);
                denom += w;
                a.x += w * vv[j].x; a.y += w * vv[j].y;
                a.z += w * vv[j].z; a.w += w * vv[j].w;
            }
            float inv = 1.0f / denom;
            uint4 o = make_uint4(f2tf(a.x * inv), f2tf(a.y * inv),
                                 f2tf(a.z * inv), f2tf(a.w * inv));
            *reinterpret_cast<uint4*>(&As[el * FSTRIDE + 4 * l16]) = o;   // always store
        }
    }
    __syncthreads();

    // ---- phase 2: GEMM 128x64x64 + residual ----
    const int wm = (wid & 3) * 32, wn = (wid >> 2) * 32;
    const int g = lane >> 2, t4 = lane & 3;
    const int j8 = lane & 7, grp = lane >> 3;

    const uint32_t As_b = (uint32_t)__cvta_generic_to_shared(As);
    const uint32_t Bs_b = (uint32_t)__cvta_generic_to_shared(Bs);
    uint32_t aAddr[2], bAddr[2];
    #pragma unroll
    for (int mt = 0; mt < 2; mt++) {
        int row = wm + mt * 16 + (grp & 1) * 8 + j8;
        int col = (grp >> 1) * 4;
        aAddr[mt] = As_b + (row * FSTRIDE + col) * 4;
    }
    #pragma unroll
    for (int p = 0; p < 2; p++) {
        int row = wn + p * 16 + (grp >> 1) * 8 + j8;
        int col = (grp & 1) * 4;
        bAddr[p] = Bs_b + (row * FSTRIDE + col) * 4;
    }

    float acc[2][4][4];
    #pragma unroll
    for (int i = 0; i < 2; i++)
        #pragma unroll
        for (int j = 0; j < 4; j++)
            #pragma unroll
            for (int q = 0; q < 4; q++) acc[i][j][q] = 0.f;

    #pragma unroll
    for (int ks = 0; ks < 8; ks++) {
        uint32_t af0[4], af1[4], bf0[4], bf1[4];
        ldsm4(af0, aAddr[0] + ks * 32);
        ldsm4(af1, aAddr[1] + ks * 32);
        ldsm4(bf0, bAddr[0] + ks * 32);
        ldsm4(bf1, bAddr[1] + ks * 32);
        mma8(acc[0][0], af0, bf0[0], bf0[1]);
        mma8(acc[0][1], af0, bf0[2], bf0[3]);
        mma8(acc[0][2], af0, bf1[0], bf1[1]);
        mma8(acc[0][3], af0, bf1[2], bf1[3]);
        mma8(acc[1][0], af1, bf0[0], bf0[1]);
        mma8(acc[1][1], af1, bf0[2], bf0[3]);
        mma8(acc[1][2], af1, bf1[0], bf1[1]);
        mma8(acc[1][3], af1, bf1[2], bf1[3]);
    }

    // ---- epilogue with residual ----
    #pragma unroll
    for (int mt = 0; mt < 2; mt++) {
        const int row = m0 + wm + mt * 16 + g;
        #pragma unroll
        for (int nt = 0; nt < 4; nt++) {
            const int col = wn + nt * 8 + t4 * 2;
            if (row < EE) {
                float2 rr = *reinterpret_cast<const float2*>(ef_in + (size_t)row * 64 + col);
                *reinterpret_cast<float2*>(out + (size_t)row * 64 + col) =
                    make_float2(rr.x + acc[mt][nt][0], rr.y + acc[mt][nt][1]);
            }
            if (row + 8 < EE) {
                float2 rr = *reinterpret_cast<const float2*>(ef_in + (size_t)(row + 8) * 64 + col);
                *reinterpret_cast<float2*>(out + (size_t)(row + 8) * 64 + col) =
                    make_float2(rr.x + acc[mt][nt][2], rr.y + acc[mt][nt][3]);
            }
        }
    }
}

// ---------------- launch ----------------
extern "C" void kernel_launch(void* const* d_in, const int* in_sizes, int n_in,
                              void* d_out, int out_size) {
    const float* nf      = (const float*)d_in[0];
    const float* ef      = (const float*)d_in[1];
    const int*   ei      = (const int*)d_in[2];
    const int*   adj_src = (const int*)d_in[4];
    const float* l1_Wq = (const float*)d_in[6];
    const float* l1_Wk = (const float*)d_in[7];
    const float* l1_Wv = (const float*)d_in[8];
    const float* l1_Wo = (const float*)d_in[9];
    const float* l2_Wq = (const float*)d_in[10];
    const float* l2_Wk = (const float*)d_in[11];
    const float* l2_Wv = (const float*)d_in[12];
    const float* l2_Wo = (const float*)d_in[13];
    float* out = (float*)d_out;

    static int attr_done = 0;
    if (!attr_done) {
        cudaFuncSetAttribute(qkv_mma_kernel, cudaFuncAttributeMaxDynamicSharedMemorySize, QKV_SMEM_BYTES);
        cudaFuncSetAttribute(attn_wo_kernel, cudaFuncAttributeMaxDynamicSharedMemorySize, FUSED_SMEM_BYTES);
        attr_done = 1;
    }

    const int gq  = (EE + 127) / 128;   // 782
    const int gf  = (EE + 127) / 128;   // 782

    // layer 1
    qkv_mma_kernel<<<gq, 256, QKV_SMEM_BYTES>>>(ef, nf, ei, l1_Wq, l1_Wk, l1_Wv, 0);
    attn_wo_kernel<<<gf, 256, FUSED_SMEM_BYTES>>>(l1_Wo, adj_src, ef, nullptr, 0, 1);

    // layer 2
    qkv_mma_kernel<<<gq, 256, QKV_SMEM_BYTES>>>(ef, nf, ei, l2_Wq, l2_Wk, l2_Wv, 1);
    attn_wo_kernel<<<gf, 256, FUSED_SMEM_BYTES>>>(l2_Wo, adj_src, nullptr, out, 1, 0);
}

// round 11
// speedup vs baseline: 1.4200x; 1.0696x over previous
#include <cuda_runtime.h>
#include <stdint.h>

#define EE     100000
#define DIN    192
#define KNB    8

// ---------------- scratch (device globals) ----------------
__device__ float g_qkv[EE * DIN];   // [E,192] = [q|k|v]
__device__ float g_ef1[EE * 64];    // [E,64] layer-1 out

// ---------------- helpers ----------------
__device__ __forceinline__ uint32_t f2tf(float x) {
    uint32_t u; asm("cvt.rna.tf32.f32 %0, %1;" : "=r"(u) : "f"(x)); return u;
}
__device__ __forceinline__ void mma8(float* c, const uint32_t* a, uint32_t b0, uint32_t b1) {
    asm volatile("mma.sync.aligned.m16n8k8.row.col.f32.tf32.tf32.f32 "
        "{%0,%1,%2,%3}, {%4,%5,%6,%7}, {%8,%9}, {%0,%1,%2,%3};"
        : "+f"(c[0]), "+f"(c[1]), "+f"(c[2]), "+f"(c[3])
        : "r"(a[0]), "r"(a[1]), "r"(a[2]), "r"(a[3]), "r"(b0), "r"(b1));
}
__device__ __forceinline__ void ldsm4(uint32_t* f, uint32_t addr) {
    asm volatile("ldmatrix.sync.aligned.m8n8.x4.shared.b16 {%0,%1,%2,%3}, [%4];"
        : "=r"(f[0]), "=r"(f[1]), "=r"(f[2]), "=r"(f[3]) : "r"(addr));
}

// ---------------- QKV kernel smem geometry (r4/r9 proven) ----------------
#define BSTRIDE    200
#define B_WORDS_F  (192 * BSTRIDE)      // 38400
#define A_WORDS    (128 * 36)           // 4608
#define QKV_SMEM_BYTES ((B_WORDS_F + 2 * A_WORDS) * 4)

// ---------------- fused attn+wo smem geometry ----------------
#define FSTRIDE    68                    // 68 % 32 == 4 -> conflict-free ldsm/STS
#define FA_WORDS   (128 * FSTRIDE)       // 8704
#define FB_WORDS   (64 * FSTRIDE)        // 4352
#define FUSED_SMEM_BYTES ((FA_WORDS + FB_WORDS) * 4)   // 52224

// ======================================================================
// Fused QKV GEMM (r4/r9 proven): qkv = concat(ef|ef1, nf[src], nf[dst]) @ [Wq|Wk|Wv]
// BM=128, BN=192, BK=32; 8 warps as 2M x 4N, warp tile 64x48.
// ======================================================================
__global__ __launch_bounds__(256, 1) void qkv_mma_kernel(
    const float* __restrict__ ef, const float* __restrict__ nf,
    const int* __restrict__ ei,
    const float* __restrict__ wq, const float* __restrict__ wk, const float* __restrict__ wv,
    int use_ef1)
{
    extern __shared__ uint32_t smem[];
    uint32_t* Bs = smem;                 // [192][200]
    uint32_t* As = smem + B_WORDS_F;     // [2][128*36]

    const int tid = threadIdx.x;
    const int m0  = blockIdx.x * 128;
    const float* efsrc = use_ef1 ? (const float*)g_ef1 : ef;

    const int r  = tid >> 1;
    const int e  = m0 + r;
    const int kb = (tid & 1) * 16;
    const bool valid = (e < EE);
    int si = 0, di = 0;
    if (valid) { si = ei[e]; di = ei[EE + e]; }

    const int wid = tid >> 5, lane = tid & 31;
    const int wm = (wid & 1) * 64, wn = (wid >> 1) * 48;
    const int g = lane >> 2, t4 = lane & 3;
    const int j8 = lane & 7, grp = lane >> 3;

    // ---- preload full B into smem (tf32) ----
    {
        #pragma unroll
        for (int w = 0; w < 3; w++) {
            const float* W = (w == 0) ? wq : (w == 1) ? wk : wv;
            #pragma unroll
            for (int j = 0; j < 12; j++) {
                int f = j * 256 + tid;
                int k = f >> 4;
                int n4 = (f & 15) * 4;
                float4 v = *reinterpret_cast<const float4*>(W + (size_t)k * 64 + n4);
                uint32_t* dst = Bs + k * BSTRIDE + w * 64 + n4;
                dst[0] = f2tf(v.x); dst[1] = f2tf(v.y);
                dst[2] = f2tf(v.z); dst[3] = f2tf(v.w);
            }
        }
    }

    const uint32_t As_b = (uint32_t)__cvta_generic_to_shared(As);
    uint32_t aAddr[4];
    #pragma unroll
    for (int mt = 0; mt < 4; mt++) {
        int row = wm + mt * 16 + (grp & 1) * 8 + j8;
        int col = (grp >> 1) * 4;
        aAddr[mt] = As_b + (row * 36 + col) * 4;
    }

    float acc[4][6][4];
    #pragma unroll
    for (int i = 0; i < 4; i++)
        #pragma unroll
        for (int j = 0; j < 6; j++)
            #pragma unroll
            for (int q = 0; q < 4; q++) acc[i][j][q] = 0.f;

    float4 av[4];
    auto ldg_tile = [&](int it) {
        const int k0 = it * 32;
        if (valid) {
            const int reg = k0 >> 6;
            const float* base = (reg == 0) ? efsrc + (size_t)e * 64
                              : (reg == 1) ? nf + (size_t)si * 64
                                           : nf + (size_t)di * 64;
            const int cb = (k0 & 32) + kb;
            #pragma unroll
            for (int c = 0; c < 4; c++) av[c] = *reinterpret_cast<const float4*>(base + cb + c * 4);
        } else {
            #pragma unroll
            for (int c = 0; c < 4; c++) av[c] = make_float4(0.f, 0.f, 0.f, 0.f);
        }
    };
    auto sts_tile = [&](int b) {
        uint32_t* Aw = As + b * A_WORDS;
        #pragma unroll
        for (int c = 0; c < 4; c++) {
            uint4 u = make_uint4(f2tf(av[c].x), f2tf(av[c].y), f2tf(av[c].z), f2tf(av[c].w));
            *reinterpret_cast<uint4*>(&Aw[r * 36 + kb + c * 4]) = u;
        }
    };

    const uint32_t* Bwp = Bs + wn + g;

    const int NIT = DIN / 32;   // 6
    ldg_tile(0);
    sts_tile(0);
    ldg_tile(1);
    __syncthreads();

    for (int i = 0; i < NIT; i++) {
        const int cur = i & 1;
        const uint32_t aOff = cur * (A_WORDS * 4);
        #pragma unroll
        for (int ks = 0; ks < 4; ks++) {
            const int kg = i * 32 + ks * 8 + t4;
            uint32_t af[4][4];
            #pragma unroll
            for (int mt = 0; mt < 4; mt++) ldsm4(af[mt], aAddr[mt] + aOff + ks * 32);
            uint32_t b0[6], b1[6];
            #pragma unroll
            for (int nt = 0; nt < 6; nt++) {
                b0[nt] = Bwp[kg * BSTRIDE + nt * 8];
                b1[nt] = Bwp[(kg + 4) * BSTRIDE + nt * 8];
            }
            #pragma unroll
            for (int mt = 0; mt < 4; mt++)
                #pragma unroll
                for (int nt = 0; nt < 6; nt++)
                    mma8(acc[mt][nt], af[mt], b0[nt], b1[nt]);
        }
        if (i + 1 < NIT) {
            sts_tile(cur ^ 1);
            if (i + 2 < NIT) ldg_tile(i + 2);
            __syncthreads();
        }
    }

    #pragma unroll
    for (int mt = 0; mt < 4; mt++) {
        const int row = m0 + wm + mt * 16 + g;
        #pragma unroll
        for (int nt = 0; nt < 6; nt++) {
            const int col = wn + nt * 8 + t4 * 2;
            if (row < EE)
                *reinterpret_cast<float2*>(g_qkv + (size_t)row * DIN + col) =
                    make_float2(acc[mt][nt][0], acc[mt][nt][1]);
            if (row + 8 < EE)
                *reinterpret_cast<float2*>(g_qkv + (size_t)(row + 8) * DIN + col) =
                    make_float2(acc[mt][nt][2], acc[mt][nt][3]);
        }
    }
}

// ======================================================================
// FUSED attention + Wo GEMM + residual — low-register two-pass attn.
// Phase 1: 128 dst edges/CTA, attention -> As tf32 (K chunked, V chunked)
// Phase 2: out = ef_in + As[128,64] @ Wo[64,64]
// ======================================================================
__global__ __launch_bounds__(256, 3) void attn_wo_kernel(
    const float* __restrict__ Wo,
    const int* __restrict__ adj_src,
    const float* __restrict__ ef_ext, float* __restrict__ out_ext,
    int use_ef1_in, int write_ef1)
{
    extern __shared__ uint32_t smem[];
    uint32_t* As = smem;                // [128][68] attention rows, tf32
    uint32_t* Bs = smem + FA_WORDS;     // [64][68]  Wo transposed [n][k], tf32

    const int tid = threadIdx.x;
    const int m0  = blockIdx.x * 128;
    const float* ef_in = use_ef1_in ? (const float*)g_ef1 : ef_ext;
    float* out = write_ef1 ? (float*)g_ef1 : out_ext;

    const int wid = tid >> 5, lane = tid & 31;

    // ---- load Wo -> Bs [n][k] (transposed, stride 68) ----
    {
        const int bk = tid & 31;
        const int bn = (tid >> 5) * 8;
        #pragma unroll
        for (int k0 = 0; k0 < 64; k0 += 32) {
            float4 bv0 = *reinterpret_cast<const float4*>(Wo + (size_t)(k0 + bk) * 64 + bn);
            float4 bv1 = *reinterpret_cast<const float4*>(Wo + (size_t)(k0 + bk) * 64 + bn + 4);
            float vv[8] = {bv0.x, bv0.y, bv0.z, bv0.w, bv1.x, bv1.y, bv1.z, bv1.w};
            #pragma unroll
            for (int j = 0; j < 8; j++)
                Bs[(bn + j) * FSTRIDE + k0 + bk] = f2tf(vv[j]);
        }
    }

    // ---- phase 1: attention into As (chunked, low-register) ----
    {
        const int sub = lane >> 4, l16 = lane & 15;
        #pragma unroll
        for (int iter = 0; iter < 8; iter++) {
            const int el = iter * 16 + wid * 2 + sub;
            const int e = m0 + el;
            const int ec = (e < EE) ? e : (EE - 1);   // clamp: keeps shuffles convergent

            const float* qrow = g_qkv + (size_t)ec * DIN;
            float4 q = *reinterpret_cast<const float4*>(qrow + 4 * l16);

            int nb[KNB];
            const int base = ec * KNB;
            #pragma unroll
            for (int j = 0; j < KNB; j++) nb[j] = adj_src[base + j];

            // pass 1: scores (K rows in chunks of 4)
            float sj[KNB];
            #pragma unroll
            for (int c = 0; c < 2; c++) {
                float4 kk[4];
                #pragma unroll
                for (int j = 0; j < 4; j++)
                    kk[j] = *reinterpret_cast<const float4*>(
                        g_qkv + (size_t)nb[c * 4 + j] * DIN + 64 + 4 * l16);
                #pragma unroll
                for (int j = 0; j < 4; j++) {
                    float p = q.x * kk[j].x + q.y * kk[j].y + q.z * kk[j].z + q.w * kk[j].w;
                    p += __shfl_xor_sync(0xffffffffu, p, 1);
                    p += __shfl_xor_sync(0xffffffffu, p, 2);   // head-local (4 lanes)
                    sj[c * 4 + j] = p * 0.25f;                  // 1/sqrt(16)
                }
            }

            float m = sj[0];
            #pragma unroll
            for (int j = 1; j < KNB; j++) m = fmaxf(m, sj[j]);

            // pass 2: weighted V accumulation (V rows in chunks of 4)
            float denom = 0.f;
            float4 a = make_float4(0.f, 0.f, 0.f, 0.f);
            #pragma unroll
            for (int c = 0; c < 2; c++) {
                float4 vv[4];
                #pragma unroll
                for (int j = 0; j < 4; j++)
                    vv[j] = *reinterpret_cast<const float4*>(
                        g_qkv + (size_t)nb[c * 4 + j] * DIN + 128 + 4 * l16);
                #pragma unroll
                for (int j = 0; j < 4; j++) {
                    float w = __expf(sj[c * 4 + j] - m);
                    denom += w;
                    a.x += w * vv[j].x; a.y += w * vv[j].y;
                    a.z += w * vv[j].z; a.w += w * vv[j].w;
                }
            }
            float inv = 1.0f / denom;
            uint4 o = make_uint4(f2tf(a.x * inv), f2tf(a.y * inv),
                                 f2tf(a.z * inv), f2tf(a.w * inv));
            *reinterpret_cast<uint4*>(&As[el * FSTRIDE + 4 * l16]) = o;
        }
    }
    __syncthreads();

    // ---- phase 2: GEMM 128x64x64 + residual ----
    const int wm = (wid & 3) * 32, wn = (wid >> 2) * 32;
    const int g = lane >> 2, t4 = lane & 3;
    const int j8 = lane & 7, grp = lane >> 3;

    const uint32_t As_b = (uint32_t)__cvta_generic_to_shared(As);
    const uint32_t Bs_b = (uint32_t)__cvta_generic_to_shared(Bs);
    uint32_t aAddr[2], bAddr[2];
    #pragma unroll
    for (int mt = 0; mt < 2; mt++) {
        int row = wm + mt * 16 + (grp & 1) * 8 + j8;
        int col = (grp >> 1) * 4;
        aAddr[mt] = As_b + (row * FSTRIDE + col) * 4;
    }
    #pragma unroll
    for (int p = 0; p < 2; p++) {
        int row = wn + p * 16 + (grp >> 1) * 8 + j8;
        int col = (grp & 1) * 4;
        bAddr[p] = Bs_b + (row * FSTRIDE + col) * 4;
    }

    float acc[2][4][4];
    #pragma unroll
    for (int i = 0; i < 2; i++)
        #pragma unroll
        for (int j = 0; j < 4; j++)
            #pragma unroll
            for (int q = 0; q < 4; q++) acc[i][j][q] = 0.f;

    #pragma unroll
    for (int ks = 0; ks < 8; ks++) {
        uint32_t af0[4], af1[4], bf0[4], bf1[4];
        ldsm4(af0, aAddr[0] + ks * 32);
        ldsm4(af1, aAddr[1] + ks * 32);
        ldsm4(bf0, bAddr[0] + ks * 32);
        ldsm4(bf1, bAddr[1] + ks * 32);
        mma8(acc[0][0], af0, bf0[0], bf0[1]);
        mma8(acc[0][1], af0, bf0[2], bf0[3]);
        mma8(acc[0][2], af0, bf1[0], bf1[1]);
        mma8(acc[0][3], af0, bf1[2], bf1[3]);
        mma8(acc[1][0], af1, bf0[0], bf0[1]);
        mma8(acc[1][1], af1, bf0[2], bf0[3]);
        mma8(acc[1][2], af1, bf1[0], bf1[1]);
        mma8(acc[1][3], af1, bf1[2], bf1[3]);
    }

    // ---- epilogue with residual ----
    #pragma unroll
    for (int mt = 0; mt < 2; mt++) {
        const int row = m0 + wm + mt * 16 + g;
        #pragma unroll
        for (int nt = 0; nt < 4; nt++) {
            const int col = wn + nt * 8 + t4 * 2;
            if (row < EE) {
                float2 rr = *reinterpret_cast<const float2*>(ef_in + (size_t)row * 64 + col);
                *reinterpret_cast<float2*>(out + (size_t)row * 64 + col) =
                    make_float2(rr.x + acc[mt][nt][0], rr.y + acc[mt][nt][1]);
            }
            if (row + 8 < EE) {
                float2 rr = *reinterpret_cast<const float2*>(ef_in + (size_t)(row + 8) * 64 + col);
                *reinterpret_cast<float2*>(out + (size_t)(row + 8) * 64 + col) =
                    make_float2(rr.x + acc[mt][nt][2], rr.y + acc[mt][nt][3]);
            }
        }
    }
}

// ---------------- launch ----------------
extern "C" void kernel_launch(void* const* d_in, const int* in_sizes, int n_in,
                              void* d_out, int out_size) {
    const float* nf      = (const float*)d_in[0];
    const float* ef      = (const float*)d_in[1];
    const int*   ei      = (const int*)d_in[2];
    const int*   adj_src = (const int*)d_in[4];
    const float* l1_Wq = (const float*)d_in[6];
    const float* l1_Wk = (const float*)d_in[7];
    const float* l1_Wv = (const float*)d_in[8];
    const float* l1_Wo = (const float*)d_in[9];
    const float* l2_Wq = (const float*)d_in[10];
    const float* l2_Wk = (const float*)d_in[11];
    const float* l2_Wv = (const float*)d_in[12];
    const float* l2_Wo = (const float*)d_in[13];
    float* out = (float*)d_out;

    static int attr_done = 0;
    if (!attr_done) {
        cudaFuncSetAttribute(qkv_mma_kernel, cudaFuncAttributeMaxDynamicSharedMemorySize, QKV_SMEM_BYTES);
        cudaFuncSetAttribute(attn_wo_kernel, cudaFuncAttributeMaxDynamicSharedMemorySize, FUSED_SMEM_BYTES);
        attr_done = 1;
    }

    const int gq = (EE + 127) / 128;   // 782
    const int gf = (EE + 127) / 128;   // 782

    // layer 1
    qkv_mma_kernel<<<gq, 256, QKV_SMEM_BYTES>>>(ef, nf, ei, l1_Wq, l1_Wk, l1_Wv, 0);
    attn_wo_kernel<<<gf, 256, FUSED_SMEM_BYTES>>>(l1_Wo, adj_src, ef, nullptr, 0, 1);

    // layer 2
    qkv_mma_kernel<<<gq, 256, QKV_SMEM_BYTES>>>(ef, nf, ei, l2_Wq, l2_Wk, l2_Wv, 1);
    attn_wo_kernel<<<gf, 256, FUSED_SMEM_BYTES>>>(l2_Wo, adj_src, nullptr, out, 1, 0);
}